// round 1
// baseline (speedup 1.0000x reference)
#include <cuda_runtime.h>
#include <cstdint>

// Problem shape (fixed by the reference)
#define NN    8192
#define CIN   256
#define COUT  128

// Scratch (allocation rules forbid cudaMalloc; __device__ globals are the
// sanctioned mechanism). 4 MB each.
__device__ float g_T[NN * COUT];   // features @ W
__device__ float g_S[NN * COUT];   // filt ⊙ (wavelets_inv @ T)

// ---- f32x2 packed-math helpers (Blackwell FFMA2: only reachable via PTX) ----
__device__ __forceinline__ unsigned long long f32x2_dup(float a) {
    unsigned long long r;
    asm("mov.b64 %0, {%1, %1};" : "=l"(r) : "f"(a));
    return r;
}
__device__ __forceinline__ unsigned long long f32x2_fma(unsigned long long a,
                                                        unsigned long long b,
                                                        unsigned long long c) {
    unsigned long long d;
    asm("fma.rn.f32x2 %0, %1, %2, %3;" : "=l"(d) : "l"(a), "l"(b), "l"(c));
    return d;
}
__device__ __forceinline__ void f32x2_unpack(unsigned long long v, float& lo, float& hi) {
    asm("mov.b64 {%0, %1}, %2;" : "=f"(lo), "=f"(hi) : "l"(v));
}

// ----------------------------------------------------------------------------
// SGEMM: C[M,128] = A[M,K] @ B[K,128]   (row-major everywhere)
// Optional per-row scale on the output (fuses diag(filt)).
// BM=64, BN=128 (= full N), BK=16, 256 threads, per-thread 4x8 micro-tile
// held as 16 packed f32x2 accumulators.
// Grid: M/64 blocks (1-D).
// ----------------------------------------------------------------------------
template<bool SCALE>
__global__ __launch_bounds__(256)
void gwnn_sgemm128(const float* __restrict__ A,
                   const float* __restrict__ B,
                   float* __restrict__ C,
                   int K,
                   const float* __restrict__ rowScale)
{
    constexpr int BM = 64, BN = 128, BK = 16, TM = 4, TN = 8;

    __shared__ float As[BK][BM];   // transposed A tile: As[k][m]
    __shared__ float Bs[BK][BN];

    const int tid  = threadIdx.x;
    const int trow = tid >> 4;          // 0..15  (micro-tile row group)
    const int tcol = tid & 15;          // 0..15  (micro-tile col group)
    const int blockM = blockIdx.x * BM;

    // A-tile load mapping: 64x16 = 1024 floats, one float4 per thread
    const int aRow = tid >> 2;          // 0..63
    const int aCol = (tid & 3) << 2;    // 0,4,8,12
    const float* Aptr = A + (size_t)(blockM + aRow) * K + aCol;

    // accumulators: acc[i][j] is a packed pair of output columns (2j, 2j+1)
    unsigned long long acc[TM][TN / 2];
    #pragma unroll
    for (int i = 0; i < TM; i++)
        #pragma unroll
        for (int j = 0; j < TN / 2; j++)
            acc[i][j] = 0ULL;

    for (int k0 = 0; k0 < K; k0 += BK) {
        // --- load A tile (transposed into SMEM) ---
        float4 av = *reinterpret_cast<const float4*>(Aptr + k0);
        As[aCol + 0][aRow] = av.x;
        As[aCol + 1][aRow] = av.y;
        As[aCol + 2][aRow] = av.z;
        As[aCol + 3][aRow] = av.w;

        // --- load B tile: 16x128 = 2048 floats, two float4 per thread ---
        #pragma unroll
        for (int i = 0; i < 2; i++) {
            int off  = tid * 4 + i * 1024;
            int bRow = off >> 7;        // /128
            int bCol = off & 127;
            *reinterpret_cast<float4*>(&Bs[bRow][bCol]) =
                *reinterpret_cast<const float4*>(B + (size_t)(k0 + bRow) * BN + bCol);
        }
        __syncthreads();

        // --- micro-kernel ---
        #pragma unroll
        for (int kk = 0; kk < BK; kk++) {
            float4 af = *reinterpret_cast<const float4*>(&As[kk][trow * TM]);
            // b fragments: LDS.128 lands in consecutive registers, so the
            // f32x2 pairs are already packed — no mov needed.
            ulonglong2 bq0 = *reinterpret_cast<const ulonglong2*>(&Bs[kk][tcol * TN]);
            ulonglong2 bq1 = *reinterpret_cast<const ulonglong2*>(&Bs[kk][tcol * TN + 4]);
            unsigned long long bp[4] = { bq0.x, bq0.y, bq1.x, bq1.y };
            float a_[4] = { af.x, af.y, af.z, af.w };

            #pragma unroll
            for (int i = 0; i < TM; i++) {
                unsigned long long ad = f32x2_dup(a_[i]);
                #pragma unroll
                for (int j = 0; j < TN / 2; j++)
                    acc[i][j] = f32x2_fma(ad, bp[j], acc[i][j]);
            }
        }
        __syncthreads();
    }

    // --- epilogue ---
    #pragma unroll
    for (int i = 0; i < TM; i++) {
        const int row = blockM + trow * TM + i;
        float s = 1.0f;
        if (SCALE) s = rowScale[row];

        float c[TN];
        #pragma unroll
        for (int j = 0; j < TN / 2; j++) {
            float lo, hi;
            f32x2_unpack(acc[i][j], lo, hi);
            c[2 * j]     = lo * s;
            c[2 * j + 1] = hi * s;
        }
        float4 v0 = make_float4(c[0], c[1], c[2], c[3]);
        float4 v1 = make_float4(c[4], c[5], c[6], c[7]);
        float* Crow = C + (size_t)row * BN + tcol * TN;
        *reinterpret_cast<float4*>(Crow)     = v0;
        *reinterpret_cast<float4*>(Crow + 4) = v1;
    }
}

// Kernel wrappers that reference the __device__ scratch directly (no
// cudaGetSymbolAddress needed — device code can take the address).
__global__ __launch_bounds__(256)
void gwnn_stage1(const float* __restrict__ features,
                 const float* __restrict__ weight)
{
    // delegate body is the same template logic — but we can't call a __global__
    // from a __global__; instead stage1 is launched via the template directly.
}

extern "C" void kernel_launch(void* const* d_in, const int* in_sizes, int n_in,
                              void* d_out, int out_size)
{
    const float* features     = (const float*)d_in[0];   // [8192, 256]
    const float* wavelets     = (const float*)d_in[1];   // [8192, 8192]
    const float* wavelets_inv = (const float*)d_in[2];   // [8192, 8192]
    const float* weight       = (const float*)d_in[3];   // [256, 128]
    const float* filt         = (const float*)d_in[4];   // [8192]
    float* out = (float*)d_out;                          // [8192, 128]

    float* T = nullptr;
    float* S = nullptr;
    // Device-global addresses: take them via a zero-cost device-symbol lookup
    // that is graph-capture safe (no stream ops, no allocation).
    cudaGetSymbolAddress((void**)&T, g_T);
    cudaGetSymbolAddress((void**)&S, g_S);

    dim3 block(256);
    dim3 grid(NN / 64);

    // Stage 1: T = features @ W          (K = 256)
    gwnn_sgemm128<false><<<grid, block>>>(features, weight, T, CIN, nullptr);
    // Stage 2: S = filt ⊙ (Wi @ T)       (K = 8192, filt fused)
    gwnn_sgemm128<true><<<grid, block>>>(wavelets_inv, T, S, NN, filt);
    // Stage 3: out = Wv @ S              (K = 8192)
    gwnn_sgemm128<false><<<grid, block>>>(wavelets, S, out, NN, nullptr);
}

// round 2
// speedup vs baseline: 1.0068x; 1.0068x over previous
#include <cuda_runtime.h>
#include <cstdint>

// Problem shape (fixed by the reference)
#define NN    8192
#define CIN   256
#define COUT  128

// Scratch (allocation rules forbid cudaMalloc; __device__ globals are the
// sanctioned mechanism). 4 MB each.
__device__ float g_T[NN * COUT];   // features @ W
__device__ float g_S[NN * COUT];   // filt ⊙ (wavelets_inv @ T)

// ---- f32x2 packed-math helpers (Blackwell FFMA2: only reachable via PTX) ----
__device__ __forceinline__ unsigned long long f32x2_dup(float a) {
    unsigned long long r;
    asm("mov.b64 %0, {%1, %1};" : "=l"(r) : "f"(a));
    return r;
}
__device__ __forceinline__ unsigned long long f32x2_fma(unsigned long long a,
                                                        unsigned long long b,
                                                        unsigned long long c) {
    unsigned long long d;
    asm("fma.rn.f32x2 %0, %1, %2, %3;" : "=l"(d) : "l"(a), "l"(b), "l"(c));
    return d;
}
__device__ __forceinline__ void f32x2_unpack(unsigned long long v, float& lo, float& hi) {
    asm("mov.b64 {%0, %1}, %2;" : "=f"(lo), "=f"(hi) : "l"(v));
}

// ----------------------------------------------------------------------------
// SGEMM: C[M,128] = A[M,K] @ B[K,128]   (row-major everywhere)
// Optional per-row scale on the output (fuses diag(filt)).
// BM=64, BN=128 (= full N), BK=16, 256 threads, per-thread 4x8 micro-tile
// held as 16 packed f32x2 accumulators.
// Grid: M/64 blocks (1-D).
// ----------------------------------------------------------------------------
template<bool SCALE>
__global__ __launch_bounds__(256)
void gwnn_sgemm128(const float* __restrict__ A,
                   const float* __restrict__ B,
                   float* __restrict__ C,
                   int K,
                   const float* __restrict__ rowScale)
{
    constexpr int BM = 64, BN = 128, BK = 16, TM = 4, TN = 8;

    __shared__ float As[BK][BM];   // transposed A tile: As[k][m]
    __shared__ float Bs[BK][BN];

    const int tid  = threadIdx.x;
    const int trow = tid >> 4;          // 0..15  (micro-tile row group)
    const int tcol = tid & 15;          // 0..15  (micro-tile col group)
    const int blockM = blockIdx.x * BM;

    // A-tile load mapping: 64x16 = 1024 floats, one float4 per thread
    const int aRow = tid >> 2;          // 0..63
    const int aCol = (tid & 3) << 2;    // 0,4,8,12
    const float* Aptr = A + (size_t)(blockM + aRow) * K + aCol;

    // accumulators: acc[i][j] is a packed pair of output columns (2j, 2j+1)
    unsigned long long acc[TM][TN / 2];
    #pragma unroll
    for (int i = 0; i < TM; i++)
        #pragma unroll
        for (int j = 0; j < TN / 2; j++)
            acc[i][j] = 0ULL;

    for (int k0 = 0; k0 < K; k0 += BK) {
        // --- load A tile (transposed into SMEM) ---
        float4 av = *reinterpret_cast<const float4*>(Aptr + k0);
        As[aCol + 0][aRow] = av.x;
        As[aCol + 1][aRow] = av.y;
        As[aCol + 2][aRow] = av.z;
        As[aCol + 3][aRow] = av.w;

        // --- load B tile: 16x128 = 2048 floats, two float4 per thread ---
        #pragma unroll
        for (int i = 0; i < 2; i++) {
            int off  = tid * 4 + i * 1024;
            int bRow = off >> 7;        // /128
            int bCol = off & 127;
            *reinterpret_cast<float4*>(&Bs[bRow][bCol]) =
                *reinterpret_cast<const float4*>(B + (size_t)(k0 + bRow) * BN + bCol);
        }
        __syncthreads();

        // --- micro-kernel ---
        #pragma unroll
        for (int kk = 0; kk < BK; kk++) {
            float4 af = *reinterpret_cast<const float4*>(&As[kk][trow * TM]);
            // b fragments: LDS.128 lands in consecutive registers, so the
            // f32x2 pairs are already packed — no mov needed.
            ulonglong2 bq0 = *reinterpret_cast<const ulonglong2*>(&Bs[kk][tcol * TN]);
            ulonglong2 bq1 = *reinterpret_cast<const ulonglong2*>(&Bs[kk][tcol * TN + 4]);
            unsigned long long bp[4] = { bq0.x, bq0.y, bq1.x, bq1.y };
            float a_[4] = { af.x, af.y, af.z, af.w };

            #pragma unroll
            for (int i = 0; i < TM; i++) {
                unsigned long long ad = f32x2_dup(a_[i]);
                #pragma unroll
                for (int j = 0; j < TN / 2; j++)
                    acc[i][j] = f32x2_fma(ad, bp[j], acc[i][j]);
            }
        }
        __syncthreads();
    }

    // --- epilogue ---
    #pragma unroll
    for (int i = 0; i < TM; i++) {
        const int row = blockM + trow * TM + i;
        float s = 1.0f;
        if (SCALE) s = rowScale[row];

        float c[TN];
        #pragma unroll
        for (int j = 0; j < TN / 2; j++) {
            float lo, hi;
            f32x2_unpack(acc[i][j], lo, hi);
            c[2 * j]     = lo * s;
            c[2 * j + 1] = hi * s;
        }
        float4 v0 = make_float4(c[0], c[1], c[2], c[3]);
        float4 v1 = make_float4(c[4], c[5], c[6], c[7]);
        float* Crow = C + (size_t)row * BN + tcol * TN;
        *reinterpret_cast<float4*>(Crow)     = v0;
        *reinterpret_cast<float4*>(Crow + 4) = v1;
    }
}

// Kernel wrappers that reference the __device__ scratch directly (no
// cudaGetSymbolAddress needed — device code can take the address).
__global__ __launch_bounds__(256)
void gwnn_stage1(const float* __restrict__ features,
                 const float* __restrict__ weight)
{
    // delegate body is the same template logic — but we can't call a __global__
    // from a __global__; instead stage1 is launched via the template directly.
}

extern "C" void kernel_launch(void* const* d_in, const int* in_sizes, int n_in,
                              void* d_out, int out_size)
{
    const float* features     = (const float*)d_in[0];   // [8192, 256]
    const float* wavelets     = (const float*)d_in[1];   // [8192, 8192]
    const float* wavelets_inv = (const float*)d_in[2];   // [8192, 8192]
    const float* weight       = (const float*)d_in[3];   // [256, 128]
    const float* filt         = (const float*)d_in[4];   // [8192]
    float* out = (float*)d_out;                          // [8192, 128]

    float* T = nullptr;
    float* S = nullptr;
    // Device-global addresses: take them via a zero-cost device-symbol lookup
    // that is graph-capture safe (no stream ops, no allocation).
    cudaGetSymbolAddress((void**)&T, g_T);
    cudaGetSymbolAddress((void**)&S, g_S);

    dim3 block(256);
    dim3 grid(NN / 64);

    // Stage 1: T = features @ W          (K = 256)
    gwnn_sgemm128<false><<<grid, block>>>(features, weight, T, CIN, nullptr);
    // Stage 2: S = filt ⊙ (Wi @ T)       (K = 8192, filt fused)
    gwnn_sgemm128<true><<<grid, block>>>(wavelets_inv, T, S, NN, filt);
    // Stage 3: out = Wv @ S              (K = 8192)
    gwnn_sgemm128<false><<<grid, block>>>(wavelets, S, out, NN, nullptr);
}

// round 3
// speedup vs baseline: 1.0070x; 1.0002x over previous
#include <cuda_runtime.h>
#include <cstdint>

// Problem shape (fixed by the reference)
#define NN    8192
#define CIN   256
#define COUT  128

// Scratch (allocation rules forbid cudaMalloc; __device__ globals are the
// sanctioned mechanism). 4 MB each.
__device__ float g_T[NN * COUT];   // features @ W
__device__ float g_S[NN * COUT];   // filt ⊙ (wavelets_inv @ T)

// ---- f32x2 packed-math helpers (Blackwell FFMA2: only reachable via PTX) ----
__device__ __forceinline__ unsigned long long f32x2_dup(float a) {
    unsigned long long r;
    asm("mov.b64 %0, {%1, %1};" : "=l"(r) : "f"(a));
    return r;
}
__device__ __forceinline__ unsigned long long f32x2_fma(unsigned long long a,
                                                        unsigned long long b,
                                                        unsigned long long c) {
    unsigned long long d;
    asm("fma.rn.f32x2 %0, %1, %2, %3;" : "=l"(d) : "l"(a), "l"(b), "l"(c));
    return d;
}
__device__ __forceinline__ void f32x2_unpack(unsigned long long v, float& lo, float& hi) {
    asm("mov.b64 {%0, %1}, %2;" : "=f"(lo), "=f"(hi) : "l"(v));
}

// ----------------------------------------------------------------------------
// SGEMM: C[M,128] = A[M,K] @ B[K,128]   (row-major everywhere)
// Optional per-row scale on the output (fuses diag(filt)).
// BM=64, BN=128 (= full N), BK=16, 256 threads, per-thread 4x8 micro-tile
// held as 16 packed f32x2 accumulators.
// Grid: M/64 blocks (1-D).
// ----------------------------------------------------------------------------
template<bool SCALE>
__global__ __launch_bounds__(256)
void gwnn_sgemm128(const float* __restrict__ A,
                   const float* __restrict__ B,
                   float* __restrict__ C,
                   int K,
                   const float* __restrict__ rowScale)
{
    constexpr int BM = 64, BN = 128, BK = 16, TM = 4, TN = 8;

    __shared__ float As[BK][BM];   // transposed A tile: As[k][m]
    __shared__ float Bs[BK][BN];

    const int tid  = threadIdx.x;
    const int trow = tid >> 4;          // 0..15  (micro-tile row group)
    const int tcol = tid & 15;          // 0..15  (micro-tile col group)
    const int blockM = blockIdx.x * BM;

    // A-tile load mapping: 64x16 = 1024 floats, one float4 per thread
    const int aRow = tid >> 2;          // 0..63
    const int aCol = (tid & 3) << 2;    // 0,4,8,12
    const float* Aptr = A + (size_t)(blockM + aRow) * K + aCol;

    // accumulators: acc[i][j] is a packed pair of output columns (2j, 2j+1)
    unsigned long long acc[TM][TN / 2];
    #pragma unroll
    for (int i = 0; i < TM; i++)
        #pragma unroll
        for (int j = 0; j < TN / 2; j++)
            acc[i][j] = 0ULL;

    for (int k0 = 0; k0 < K; k0 += BK) {
        // --- load A tile (transposed into SMEM) ---
        float4 av = *reinterpret_cast<const float4*>(Aptr + k0);
        As[aCol + 0][aRow] = av.x;
        As[aCol + 1][aRow] = av.y;
        As[aCol + 2][aRow] = av.z;
        As[aCol + 3][aRow] = av.w;

        // --- load B tile: 16x128 = 2048 floats, two float4 per thread ---
        #pragma unroll
        for (int i = 0; i < 2; i++) {
            int off  = tid * 4 + i * 1024;
            int bRow = off >> 7;        // /128
            int bCol = off & 127;
            *reinterpret_cast<float4*>(&Bs[bRow][bCol]) =
                *reinterpret_cast<const float4*>(B + (size_t)(k0 + bRow) * BN + bCol);
        }
        __syncthreads();

        // --- micro-kernel ---
        #pragma unroll
        for (int kk = 0; kk < BK; kk++) {
            float4 af = *reinterpret_cast<const float4*>(&As[kk][trow * TM]);
            // b fragments: LDS.128 lands in consecutive registers, so the
            // f32x2 pairs are already packed — no mov needed.
            ulonglong2 bq0 = *reinterpret_cast<const ulonglong2*>(&Bs[kk][tcol * TN]);
            ulonglong2 bq1 = *reinterpret_cast<const ulonglong2*>(&Bs[kk][tcol * TN + 4]);
            unsigned long long bp[4] = { bq0.x, bq0.y, bq1.x, bq1.y };
            float a_[4] = { af.x, af.y, af.z, af.w };

            #pragma unroll
            for (int i = 0; i < TM; i++) {
                unsigned long long ad = f32x2_dup(a_[i]);
                #pragma unroll
                for (int j = 0; j < TN / 2; j++)
                    acc[i][j] = f32x2_fma(ad, bp[j], acc[i][j]);
            }
        }
        __syncthreads();
    }

    // --- epilogue ---
    #pragma unroll
    for (int i = 0; i < TM; i++) {
        const int row = blockM + trow * TM + i;
        float s = 1.0f;
        if (SCALE) s = rowScale[row];

        float c[TN];
        #pragma unroll
        for (int j = 0; j < TN / 2; j++) {
            float lo, hi;
            f32x2_unpack(acc[i][j], lo, hi);
            c[2 * j]     = lo * s;
            c[2 * j + 1] = hi * s;
        }
        float4 v0 = make_float4(c[0], c[1], c[2], c[3]);
        float4 v1 = make_float4(c[4], c[5], c[6], c[7]);
        float* Crow = C + (size_t)row * BN + tcol * TN;
        *reinterpret_cast<float4*>(Crow)     = v0;
        *reinterpret_cast<float4*>(Crow + 4) = v1;
    }
}

// Kernel wrappers that reference the __device__ scratch directly (no
// cudaGetSymbolAddress needed — device code can take the address).
__global__ __launch_bounds__(256)
void gwnn_stage1(const float* __restrict__ features,
                 const float* __restrict__ weight)
{
    // delegate body is the same template logic — but we can't call a __global__
    // from a __global__; instead stage1 is launched via the template directly.
}

extern "C" void kernel_launch(void* const* d_in, const int* in_sizes, int n_in,
                              void* d_out, int out_size)
{
    const float* features     = (const float*)d_in[0];   // [8192, 256]
    const float* wavelets     = (const float*)d_in[1];   // [8192, 8192]
    const float* wavelets_inv = (const float*)d_in[2];   // [8192, 8192]
    const float* weight       = (const float*)d_in[3];   // [256, 128]
    const float* filt         = (const float*)d_in[4];   // [8192]
    float* out = (float*)d_out;                          // [8192, 128]

    float* T = nullptr;
    float* S = nullptr;
    // Device-global addresses: take them via a zero-cost device-symbol lookup
    // that is graph-capture safe (no stream ops, no allocation).
    cudaGetSymbolAddress((void**)&T, g_T);
    cudaGetSymbolAddress((void**)&S, g_S);

    dim3 block(256);
    dim3 grid(NN / 64);

    // Stage 1: T = features @ W          (K = 256)
    gwnn_sgemm128<false><<<grid, block>>>(features, weight, T, CIN, nullptr);
    // Stage 2: S = filt ⊙ (Wi @ T)       (K = 8192, filt fused)
    gwnn_sgemm128<true><<<grid, block>>>(wavelets_inv, T, S, NN, filt);
    // Stage 3: out = Wv @ S              (K = 8192)
    gwnn_sgemm128<false><<<grid, block>>>(wavelets, S, out, NN, nullptr);
}

// round 5
// speedup vs baseline: 1.0075x; 1.0005x over previous
#include <cuda_runtime.h>
#include <cstdint>

// Problem shape (fixed by the reference)
#define NN    8192
#define CIN   256
#define COUT  128

// Scratch (allocation rules forbid cudaMalloc; __device__ globals are the
// sanctioned mechanism). 4 MB each.
__device__ float g_T[NN * COUT];   // features @ W
__device__ float g_S[NN * COUT];   // filt ⊙ (wavelets_inv @ T)

// ---- f32x2 packed-math helpers (Blackwell FFMA2: only reachable via PTX) ----
__device__ __forceinline__ unsigned long long f32x2_dup(float a) {
    unsigned long long r;
    asm("mov.b64 %0, {%1, %1};" : "=l"(r) : "f"(a));
    return r;
}
__device__ __forceinline__ unsigned long long f32x2_fma(unsigned long long a,
                                                        unsigned long long b,
                                                        unsigned long long c) {
    unsigned long long d;
    asm("fma.rn.f32x2 %0, %1, %2, %3;" : "=l"(d) : "l"(a), "l"(b), "l"(c));
    return d;
}
__device__ __forceinline__ void f32x2_unpack(unsigned long long v, float& lo, float& hi) {
    asm("mov.b64 {%0, %1}, %2;" : "=f"(lo), "=f"(hi) : "l"(v));
}

// ----------------------------------------------------------------------------
// SGEMM: C[M,128] = A[M,K] @ B[K,128]   (row-major everywhere)
// Optional per-row scale on the output (fuses diag(filt)).
// BM=64, BN=128 (= full N), BK=16, 256 threads, per-thread 4x8 micro-tile
// held as 16 packed f32x2 accumulators.
// Grid: M/64 blocks (1-D).
// ----------------------------------------------------------------------------
template<bool SCALE>
__global__ __launch_bounds__(256)
void gwnn_sgemm128(const float* __restrict__ A,
                   const float* __restrict__ B,
                   float* __restrict__ C,
                   int K,
                   const float* __restrict__ rowScale)
{
    constexpr int BM = 64, BN = 128, BK = 16, TM = 4, TN = 8;

    __shared__ float As[BK][BM];   // transposed A tile: As[k][m]
    __shared__ float Bs[BK][BN];

    const int tid  = threadIdx.x;
    const int trow = tid >> 4;          // 0..15  (micro-tile row group)
    const int tcol = tid & 15;          // 0..15  (micro-tile col group)
    const int blockM = blockIdx.x * BM;

    // A-tile load mapping: 64x16 = 1024 floats, one float4 per thread
    const int aRow = tid >> 2;          // 0..63
    const int aCol = (tid & 3) << 2;    // 0,4,8,12
    const float* Aptr = A + (size_t)(blockM + aRow) * K + aCol;

    // accumulators: acc[i][j] is a packed pair of output columns (2j, 2j+1)
    unsigned long long acc[TM][TN / 2];
    #pragma unroll
    for (int i = 0; i < TM; i++)
        #pragma unroll
        for (int j = 0; j < TN / 2; j++)
            acc[i][j] = 0ULL;

    for (int k0 = 0; k0 < K; k0 += BK) {
        // --- load A tile (transposed into SMEM) ---
        float4 av = *reinterpret_cast<const float4*>(Aptr + k0);
        As[aCol + 0][aRow] = av.x;
        As[aCol + 1][aRow] = av.y;
        As[aCol + 2][aRow] = av.z;
        As[aCol + 3][aRow] = av.w;

        // --- load B tile: 16x128 = 2048 floats, two float4 per thread ---
        #pragma unroll
        for (int i = 0; i < 2; i++) {
            int off  = tid * 4 + i * 1024;
            int bRow = off >> 7;        // /128
            int bCol = off & 127;
            *reinterpret_cast<float4*>(&Bs[bRow][bCol]) =
                *reinterpret_cast<const float4*>(B + (size_t)(k0 + bRow) * BN + bCol);
        }
        __syncthreads();

        // --- micro-kernel ---
        #pragma unroll
        for (int kk = 0; kk < BK; kk++) {
            float4 af = *reinterpret_cast<const float4*>(&As[kk][trow * TM]);
            // b fragments: LDS.128 lands in consecutive registers, so the
            // f32x2 pairs are already packed — no mov needed.
            ulonglong2 bq0 = *reinterpret_cast<const ulonglong2*>(&Bs[kk][tcol * TN]);
            ulonglong2 bq1 = *reinterpret_cast<const ulonglong2*>(&Bs[kk][tcol * TN + 4]);
            unsigned long long bp[4] = { bq0.x, bq0.y, bq1.x, bq1.y };
            float a_[4] = { af.x, af.y, af.z, af.w };

            #pragma unroll
            for (int i = 0; i < TM; i++) {
                unsigned long long ad = f32x2_dup(a_[i]);
                #pragma unroll
                for (int j = 0; j < TN / 2; j++)
                    acc[i][j] = f32x2_fma(ad, bp[j], acc[i][j]);
            }
        }
        __syncthreads();
    }

    // --- epilogue ---
    #pragma unroll
    for (int i = 0; i < TM; i++) {
        const int row = blockM + trow * TM + i;
        float s = 1.0f;
        if (SCALE) s = rowScale[row];

        float c[TN];
        #pragma unroll
        for (int j = 0; j < TN / 2; j++) {
            float lo, hi;
            f32x2_unpack(acc[i][j], lo, hi);
            c[2 * j]     = lo * s;
            c[2 * j + 1] = hi * s;
        }
        float4 v0 = make_float4(c[0], c[1], c[2], c[3]);
        float4 v1 = make_float4(c[4], c[5], c[6], c[7]);
        float* Crow = C + (size_t)row * BN + tcol * TN;
        *reinterpret_cast<float4*>(Crow)     = v0;
        *reinterpret_cast<float4*>(Crow + 4) = v1;
    }
}

// Kernel wrappers that reference the __device__ scratch directly (no
// cudaGetSymbolAddress needed — device code can take the address).
__global__ __launch_bounds__(256)
void gwnn_stage1(const float* __restrict__ features,
                 const float* __restrict__ weight)
{
    // delegate body is the same template logic — but we can't call a __global__
    // from a __global__; instead stage1 is launched via the template directly.
}

extern "C" void kernel_launch(void* const* d_in, const int* in_sizes, int n_in,
                              void* d_out, int out_size)
{
    const float* features     = (const float*)d_in[0];   // [8192, 256]
    const float* wavelets     = (const float*)d_in[1];   // [8192, 8192]
    const float* wavelets_inv = (const float*)d_in[2];   // [8192, 8192]
    const float* weight       = (const float*)d_in[3];   // [256, 128]
    const float* filt         = (const float*)d_in[4];   // [8192]
    float* out = (float*)d_out;                          // [8192, 128]

    float* T = nullptr;
    float* S = nullptr;
    // Device-global addresses: take them via a zero-cost device-symbol lookup
    // that is graph-capture safe (no stream ops, no allocation).
    cudaGetSymbolAddress((void**)&T, g_T);
    cudaGetSymbolAddress((void**)&S, g_S);

    dim3 block(256);
    dim3 grid(NN / 64);

    // Stage 1: T = features @ W          (K = 256)
    gwnn_sgemm128<false><<<grid, block>>>(features, weight, T, CIN, nullptr);
    // Stage 2: S = filt ⊙ (Wi @ T)       (K = 8192, filt fused)
    gwnn_sgemm128<true><<<grid, block>>>(wavelets_inv, T, S, NN, filt);
    // Stage 3: out = Wv @ S              (K = 8192)
    gwnn_sgemm128<false><<<grid, block>>>(wavelets, S, out, NN, nullptr);
}